// round 16
// baseline (speedup 1.0000x reference)
#include <cuda_runtime.h>
#include <cuda_fp16.h>
#include <math.h>

#define BB 256       // batch
#define TT 256       // timesteps
#define FF 511       // raw feature dim
#define UU 512       // units
#define ZZ 2048      // 4*U (gate-interleaved cols: n' = 4u + gate)
#define KK 1024      // decoder fused K
#define GRID 128
#define THR 256      // prep/zx block
#define THRP 512     // persistent kernels: 16 warps
#define AST2 136     // A smem stage stride (halfs), 128-K stages

// ---------------- device scratch ----------------
__device__ float  g_Xt[(size_t)TT * BB * UU];
__device__ float  g_Zx[(size_t)TT * BB * ZZ];
__device__ __half g_encH[(size_t)BB * TT * UU];
__device__ float  g_Wxe[(size_t)UU * ZZ];
__device__ __half g_WheT[(size_t)ZZ * UU];
__device__ __half g_WdT[(size_t)ZZ * KK];
__device__ float  g_Bdec[ZZ];
__device__ __half g_AhH[2][BB * UU];
__device__ __half g_AdH[2][BB * KK];
__device__ float  g_h[BB * UU];
__device__ float  g_c[BB * UU];
__device__ float  g_x0[BB * UU];
__device__ unsigned g_gcnt[4][32];   // per-rowgroup arrive counters, 128B apart
__device__ unsigned g_gflag[4][32];  // per-rowgroup release flags, 128B apart

// ---------------- helpers ----------------
__device__ __forceinline__ float tf32r(float x) {
    unsigned r; asm("cvt.rna.tf32.f32 %0, %1;" : "=r"(r) : "f"(x));
    return __uint_as_float(r);
}
__device__ __forceinline__ float sigf(float x) { return 1.0f / (1.0f + __expf(-x)); }
__device__ __forceinline__ float tanhx(float x) { return 2.0f / (1.0f + __expf(-2.0f * x)) - 1.0f; }
__device__ __forceinline__ void h2f(unsigned v, float& a, float& b) {
    float2 f = __half22float2(*reinterpret_cast<const __half2*>(&v));
    a = f.x; b = f.y;
}
__device__ __forceinline__ void cvt16(const uint4 E[2], float ex[16]) {
    h2f(E[0].x, ex[0], ex[1]);   h2f(E[0].y, ex[2], ex[3]);
    h2f(E[0].z, ex[4], ex[5]);   h2f(E[0].w, ex[6], ex[7]);
    h2f(E[1].x, ex[8], ex[9]);   h2f(E[1].y, ex[10], ex[11]);
    h2f(E[1].z, ex[12], ex[13]); h2f(E[1].w, ex[14], ex[15]);
}

// 32-CTA row-group barrier (R15): all cross-CTA deps are group-local.
__device__ __forceinline__ void gsync(unsigned target) {
    __syncthreads();
    if (threadIdx.x == 0) {
        const int g = blockIdx.x >> 5;
        unsigned old;
        asm volatile("atom.add.acq_rel.gpu.u32 %0, [%1], 1;"
                     : "=r"(old) : "l"(&g_gcnt[g][0]) : "memory");
        if (old == 31u) {
            g_gcnt[g][0] = 0u;                 // published by the release below
            asm volatile("st.release.gpu.u32 [%0], %1;"
                         :: "l"(&g_gflag[g][0]), "r"(target) : "memory");
        } else {
            unsigned v;
            do {
                asm volatile("ld.acquire.gpu.u32 %0, [%1];"
                             : "=r"(v) : "l"(&g_gflag[g][0]) : "memory");
            } while (v < target);
        }
    }
    __syncthreads();
}

__device__ __forceinline__ void mma_tf32(float d[4], const unsigned a[4], const unsigned b[2]) {
    asm volatile("mma.sync.aligned.m16n8k8.row.col.f32.tf32.tf32.f32 "
                 "{%0,%1,%2,%3}, {%4,%5,%6,%7}, {%8,%9}, {%0,%1,%2,%3};\n"
                 : "+f"(d[0]), "+f"(d[1]), "+f"(d[2]), "+f"(d[3])
                 : "r"(a[0]), "r"(a[1]), "r"(a[2]), "r"(a[3]), "r"(b[0]), "r"(b[1]));
}
__device__ __forceinline__ void mma_f16(float d[4], const unsigned a[4], const unsigned b[2]) {
    asm volatile("mma.sync.aligned.m16n8k16.row.col.f32.f16.f16.f32 "
                 "{%0,%1,%2,%3}, {%4,%5,%6,%7}, {%8,%9}, {%0,%1,%2,%3};\n"
                 : "+f"(d[0]), "+f"(d[1]), "+f"(d[2]), "+f"(d[3])
                 : "r"(a[0]), "r"(a[1]), "r"(a[2]), "r"(a[3]), "r"(b[0]), "r"(b[1]));
}
__device__ __forceinline__ void ldsm_x4(unsigned& r0, unsigned& r1, unsigned& r2, unsigned& r3,
                                        unsigned addr) {
    asm volatile("ldmatrix.sync.aligned.m8n8.x4.shared.b16 {%0,%1,%2,%3}, [%4];"
                 : "=r"(r0), "=r"(r1), "=r"(r2), "=r"(r3) : "r"(addr));
}
__device__ __forceinline__ void cpasync16(unsigned sdst, const void* gsrc) {
    asm volatile("cp.async.cg.shared.global [%0], [%1], 16;"
                 :: "r"(sdst), "l"(gsrc) : "memory");
}

// ---------------- prep ----------------
__global__ void prepA_kernel(const float* __restrict__ inputs, const float* __restrict__ score,
                             const float* __restrict__ eWx, const float* __restrict__ eWh,
                             const float* __restrict__ dWx, const float* __restrict__ dWh,
                             const float* __restrict__ db) {
    size_t idx = (size_t)blockIdx.x * blockDim.x + threadIdx.x;
    if (idx < (size_t)KK * ZZ) {
        int k = (int)(idx / ZZ), np = (int)(idx % ZZ);
        int n = (np & 3) * UU + (np >> 2);
        float v = (k < UU) ? dWx[(size_t)k * ZZ + n] : dWh[(size_t)(k - UU) * ZZ + n];
        g_WdT[(size_t)np * KK + k] = __float2half_rn(v);
    }
    if (idx < (size_t)UU * ZZ) {
        int k = (int)(idx / ZZ), np = (int)(idx % ZZ);
        int n = (np & 3) * UU + (np >> 2);
        g_Wxe[idx] = tf32r(eWx[(size_t)k * ZZ + n]);
        g_WheT[(size_t)np * UU + k] = __float2half_rn(eWh[(size_t)k * ZZ + n]);
    }
    if (idx < ZZ) g_Bdec[idx] = db[((int)idx & 3) * UU + ((int)idx >> 2)];
    if (idx < BB * UU) {
        int i = (int)idx;
        g_AhH[0][i] = __float2half_rn(0.f);
        g_c[i] = 0.f;
        int b = i >> 9, u = i & 511;
        float s;
        if (u < FF) {
            const float* ip = inputs + (size_t)b * TT * FF + u;
            float acc = 0.f;
            #pragma unroll 4
            for (int t = 0; t < TT; t++) acc += ip[(size_t)t * FF];
            s = acc * (1.0f / TT);
        } else {
            s = score[b];
        }
        g_x0[i] = s;
    }
    if (idx < 128) {
        ((unsigned*)g_gcnt)[idx] = 0u;
        ((unsigned*)g_gflag)[idx] = 0u;
    }
}

__global__ void prepX_kernel(const float* __restrict__ inputs, const float* __restrict__ score) {
    size_t idx = (size_t)blockIdx.x * blockDim.x + threadIdx.x;
    if (idx >= (size_t)TT * BB * UU) return;
    int t = (int)(idx / (BB * UU));
    int rem = (int)(idx % (BB * UU));
    int b = rem / UU, u = rem % UU;
    float v = (u < FF) ? inputs[((size_t)b * TT + t) * FF + u] : score[b];
    g_Xt[idx] = tf32r(v);
}

// ---------------- Zx = X @ Wxe + bias ----------------
__global__ void __launch_bounds__(256) zx_kernel(const float* __restrict__ be) {
    __shared__ float SAx[2][128 * 20];
    __shared__ float SBx[2][16 * 72];
    const int tid = threadIdx.x, lane = tid & 31, wid = tid >> 5;
    const int rowBase = blockIdx.y << 7;
    const int colBase = blockIdx.x << 6;
    const int mB = (wid >> 1) << 5;
    const int nB = (wid & 1) << 5;
    const int gq = lane >> 2, tq = lane & 3;

    const int ar = tid >> 2;
    const int akq = (tid & 3) << 2;
    const int bkr = tid >> 4, bnq = (tid & 15) << 2;
    const float* aptrA = g_Xt + (size_t)(rowBase + ar) * UU + akq;
    const float* aptrB = aptrA + (size_t)64 * UU;
    const float* bptr = g_Wxe + (size_t)bkr * ZZ + colBase + bnq;

    float4 rAa0 = *(const float4*)(aptrA);
    float4 rAb0 = *(const float4*)(aptrB);
    float4 rB0  = *(const float4*)(bptr);
    float4 rAa1 = *(const float4*)(aptrA + 16);
    float4 rAb1 = *(const float4*)(aptrB + 16);
    float4 rB1  = *(const float4*)(bptr + (size_t)16 * ZZ);
    *(float4*)&SAx[0][ar * 20 + akq] = rAa0;
    *(float4*)&SAx[0][(64 + ar) * 20 + akq] = rAb0;
    *(float4*)&SBx[0][bkr * 72 + bnq] = rB0;
    __syncthreads();

    float d[2][4][4];
    #pragma unroll
    for (int i = 0; i < 2; i++)
        #pragma unroll
        for (int j = 0; j < 4; j++)
            #pragma unroll
            for (int q = 0; q < 4; q++) d[i][j][q] = 0.f;

    #pragma unroll 1
    for (int kt = 0; kt < 32; kt += 2) {
        if (kt + 2 < 32) {
            rAa0 = *(const float4*)(aptrA + (kt + 2) * 16);
            rAb0 = *(const float4*)(aptrB + (kt + 2) * 16);
            rB0  = *(const float4*)(bptr + (size_t)(kt + 2) * 16 * ZZ);
        }
        #pragma unroll
        for (int kc = 0; kc < 16; kc += 8) {
            unsigned a0[4], a1[4], bbf[4][2];
            const float* A0 = SAx[0] + (mB + gq) * 20 + kc + tq;
            a0[0] = __float_as_uint(A0[0]);      a0[1] = __float_as_uint(A0[8 * 20]);
            a0[2] = __float_as_uint(A0[4]);      a0[3] = __float_as_uint(A0[8 * 20 + 4]);
            const float* A1 = A0 + 16 * 20;
            a1[0] = __float_as_uint(A1[0]);      a1[1] = __float_as_uint(A1[8 * 20]);
            a1[2] = __float_as_uint(A1[4]);      a1[3] = __float_as_uint(A1[8 * 20 + 4]);
            const float* B0 = SBx[0] + (kc + tq) * 72 + nB + gq;
            #pragma unroll
            for (int ns = 0; ns < 4; ns++) {
                bbf[ns][0] = __float_as_uint(B0[ns * 8]);
                bbf[ns][1] = __float_as_uint(B0[4 * 72 + ns * 8]);
            }
            #pragma unroll
            for (int ns = 0; ns < 4; ns++) { mma_tf32(d[0][ns], a0, bbf[ns]); mma_tf32(d[1][ns], a1, bbf[ns]); }
        }
        *(float4*)&SAx[1][ar * 20 + akq] = rAa1;
        *(float4*)&SAx[1][(64 + ar) * 20 + akq] = rAb1;
        *(float4*)&SBx[1][bkr * 72 + bnq] = rB1;
        __syncthreads();

        if (kt + 3 < 32) {
            rAa1 = *(const float4*)(aptrA + (kt + 3) * 16);
            rAb1 = *(const float4*)(aptrB + (kt + 3) * 16);
            rB1  = *(const float4*)(bptr + (size_t)(kt + 3) * 16 * ZZ);
        }
        #pragma unroll
        for (int kc = 0; kc < 16; kc += 8) {
            unsigned a0[4], a1[4], bbf[4][2];
            const float* A0 = SAx[1] + (mB + gq) * 20 + kc + tq;
            a0[0] = __float_as_uint(A0[0]);      a0[1] = __float_as_uint(A0[8 * 20]);
            a0[2] = __float_as_uint(A0[4]);      a0[3] = __float_as_uint(A0[8 * 20 + 4]);
            const float* A1 = A0 + 16 * 20;
            a1[0] = __float_as_uint(A1[0]);      a1[1] = __float_as_uint(A1[8 * 20]);
            a1[2] = __float_as_uint(A1[4]);      a1[3] = __float_as_uint(A1[8 * 20 + 4]);
            const float* B0 = SBx[1] + (kc + tq) * 72 + nB + gq;
            #pragma unroll
            for (int ns = 0; ns < 4; ns++) {
                bbf[ns][0] = __float_as_uint(B0[ns * 8]);
                bbf[ns][1] = __float_as_uint(B0[4 * 72 + ns * 8]);
            }
            #pragma unroll
            for (int ns = 0; ns < 4; ns++) { mma_tf32(d[0][ns], a0, bbf[ns]); mma_tf32(d[1][ns], a1, bbf[ns]); }
        }
        if (kt + 2 < 32) {
            *(float4*)&SAx[0][ar * 20 + akq] = rAa0;
            *(float4*)&SAx[0][(64 + ar) * 20 + akq] = rAb0;
            *(float4*)&SBx[0][bkr * 72 + bnq] = rB0;
        }
        __syncthreads();
    }

    #pragma unroll
    for (int ms = 0; ms < 2; ms++) {
        #pragma unroll
        for (int ns = 0; ns < 4; ns++) {
            int r0 = rowBase + mB + ms * 16 + gq;
            int c0 = colBase + nB + ns * 8 + 2 * tq;
            int g0 = c0 & 3, u = c0 >> 2;
            float b0 = be[g0 * UU + u], b1 = be[(g0 + 1) * UU + u];
            float2 o1 = { d[ms][ns][0] + b0, d[ms][ns][1] + b1 };
            float2 o2 = { d[ms][ns][2] + b0, d[ms][ns][3] + b1 };
            *(float2*)&g_Zx[(size_t)r0 * ZZ + c0] = o1;
            *(float2*)&g_Zx[(size_t)(r0 + 8) * ZZ + c0] = o2;
        }
    }
}

// ---------------- 16-warp fp16 W-stationary GEMM: 128-K stages, cp.async ring-4 ----------------
template<int KD>
__device__ __forceinline__ void gemm_f16_loop(const __half* __restrict__ Acta,
                                              const __half* __restrict__ WS,
                                              __half* __restrict__ SA,
                                              float d[2][4]) {
    const int tid = threadIdx.x, lane = tid & 31, wid = tid >> 5;
    const int mB = (wid >> 2) << 4;
    const int nB = (wid & 3) << 4;
    const int WSTR = KD + 8;
    const int aRow = (lane & 7) + ((lane >> 3) & 1) * 8;
    const int aK   = (lane >> 4) << 3;
    const int bN   = ((lane >> 4) << 3) + (lane & 7);
    const int bK   = ((lane >> 3) & 1) << 3;

    unsigned saBase = (unsigned)__cvta_generic_to_shared(SA);
    unsigned wsAddr = (unsigned)__cvta_generic_to_shared(WS)
                    + (unsigned)(((nB + bN) * WSTR + bK) * 2);
    unsigned aAddr = saBase + (unsigned)(((mB + aRow) * AST2 + aK) * 2);

    const int r = tid >> 3, j8 = (tid & 7) << 3;   // 64 rows x 128 halfs, 2 uint4/thread
    const __half* ap = Acta + (size_t)r * KD + j8;
    const unsigned sdst = saBase + (unsigned)((r * AST2 + j8) * 2);
    const unsigned SLOT = (unsigned)(64 * AST2 * 2);

    constexpr int S = KD / 128;                    // 4 (enc) / 8 (dec)
    // prologue: stages 0,1 in flight as groups 0,1
    cpasync16(sdst, ap);
    cpasync16(sdst + 128, ap + 64);
    asm volatile("cp.async.commit_group;" ::: "memory");
    cpasync16(sdst + SLOT, ap + 128);
    cpasync16(sdst + SLOT + 128, ap + 192);
    asm volatile("cp.async.commit_group;" ::: "memory");

    #pragma unroll 1
    for (int s = 0; s < S; s++) {
        if (s + 2 < S) {
            unsigned dsl = sdst + (unsigned)((s + 2) & 3) * SLOT;
            const __half* gp = ap + (s + 2) * 128;
            cpasync16(dsl, gp);
            cpasync16(dsl + 128, gp + 64);
        }
        asm volatile("cp.async.commit_group;" ::: "memory");
        asm volatile("cp.async.wait_group 2;" ::: "memory");
        __syncthreads();

        unsigned sa = aAddr + (unsigned)(s & 3) * SLOT;
        unsigned wk = wsAddr + (unsigned)((s << 7) * 2);
        #pragma unroll
        for (int kc = 0; kc < 128; kc += 16) {
            unsigned a0[4], bb[4];
            ldsm_x4(a0[0], a0[1], a0[2], a0[3], sa + kc * 2);
            ldsm_x4(bb[0], bb[1], bb[2], bb[3], wk + kc * 2);
            unsigned b0[2] = { bb[0], bb[1] };
            unsigned b1[2] = { bb[2], bb[3] };
            mma_f16(d[0], a0, b0);
            mma_f16(d[1], a0, b1);
        }
    }
    __syncthreads();
}

// ---------------- persistent encoder (512 threads) ----------------
#define ENC_WS_H (64 * (UU + 8))
#define ENC_SA_H (4 * 64 * AST2)
#define ENC_SMEM ((ENC_WS_H + ENC_SA_H) * 2)

__global__ void __launch_bounds__(THRP, 1) encoder_kernel() {
    extern __shared__ __half es[];
    __half* WS = es;
    __half* SA = es + ENC_WS_H;

    const int tid = threadIdx.x, lane = tid & 31, wid = tid >> 5;
    const int rowBase = (blockIdx.x >> 5) << 6;
    const int colBase = (blockIdx.x & 31) << 6;
    const int mB = (wid >> 2) << 4;
    const int nB = (wid & 3) << 4;
    const int gq = lane >> 2, tq = lane & 3;

    for (int j = tid; j < 64 * 64; j += THRP) {
        int row = j >> 6, ch = (j & 63) << 3;
        *(uint4*)&WS[row * (UU + 8) + ch] =
            *(const uint4*)&g_WheT[(size_t)(colBase + row) * UU + ch];
    }
    __syncthreads();

    unsigned gen = 0;
    for (int t = 0; t < TT; t++) {
        const __half* Acta = g_AhH[t & 1] + (size_t)rowBase * UU;
        __half* An = g_AhH[(t + 1) & 1];

        float d[2][4];
        #pragma unroll
        for (int j = 0; j < 2; j++)
            #pragma unroll
            for (int q = 0; q < 4; q++) d[j][q] = 0.f;

        gemm_f16_loop<UU>(Acta, WS, SA, d);

        #pragma unroll
        for (int ns = 0; ns < 2; ns++) {
            int r0 = rowBase + mB + gq;
            int c0 = colBase + nB + ns * 8 + 2 * tq;
            const float* zx = &g_Zx[((size_t)t * BB + r0) * ZZ + c0];
            float2 zxa = *(const float2*)zx;
            float2 zxb = *(const float2*)(zx + (size_t)8 * ZZ);
            float z0 = d[ns][0] + zxa.x;
            float z1 = d[ns][1] + zxa.y;
            float z2 = d[ns][2] + zxb.x;
            float z3 = d[ns][3] + zxb.y;
            float p0 = __shfl_xor_sync(0xffffffffu, z0, 1);
            float p1 = __shfl_xor_sync(0xffffffffu, z1, 1);
            float p2 = __shfl_xor_sync(0xffffffffu, z2, 1);
            float p3 = __shfl_xor_sync(0xffffffffu, z3, 1);
            if (!(tq & 1)) {
                int u = c0 >> 2;
                #pragma unroll
                for (int rr = 0; rr < 2; rr++) {
                    int b = r0 + rr * 8;
                    float zi = rr ? z2 : z0, zf = rr ? z3 : z1;
                    float zg = rr ? p2 : p0, zo = rr ? p3 : p1;
                    int idx = b * UU + u;
                    float c = sigf(zf) * g_c[idx] + sigf(zi) * tanhx(zg);
                    float h = sigf(zo) * tanhx(c);
                    g_c[idx] = c;
                    __half hh = __float2half_rn(h);
                    An[idx] = hh;
                    g_encH[((size_t)b * TT + t) * UU + u] = hh;
                }
            }
        }
        gsync(++gen);
    }
}

// ---------------- decoder prologue ----------------
__global__ void decprep_kernel() {
    int idx = blockIdx.x * THR + threadIdx.x;
    if (idx >= BB * UU) return;
    int b = idx >> 9, u = idx & 511;
    g_AdH[0][b * KK + u] = __float2half_rn(g_x0[idx]);
    g_AdH[0][b * KK + UU + u] = g_AhH[0][idx];
}

// ---------------- persistent decoder (512 threads, wctx aliased onto SA ring) ----------------
#define DEC_WS_H (64 * (KK + 8))
#define DEC_SA_H (4 * 64 * AST2)
#define DEC_SMEM ((DEC_WS_H + DEC_SA_H) * 2 + (2 * TT + 40) * 4)

__global__ void __launch_bounds__(THRP, 1) decoder_kernel(
    const float* __restrict__ ptr_w, const float* __restrict__ ptr_b,
    float* __restrict__ out) {
    extern __shared__ __half ds[];
    __half* WS = ds;
    __half* SA = ds + DEC_WS_H;
    float* wctx = (float*)SA;                           // [16][512] aliased: SA dead in attention phase
    float* sc   = (float*)(ds + DEC_WS_H + DEC_SA_H);   // [2][256]
    float* wm   = sc + 2 * TT;                          // [16]
    float* wz   = wm + 16;                              // [16]

    const int tid = threadIdx.x, lane = tid & 31, warp = tid >> 5;
    const int rowBase = (blockIdx.x >> 5) << 6;
    const int colBase = (blockIdx.x & 31) << 6;
    const int mB = (warp >> 2) << 4;
    const int nB = (warp & 3) << 4;
    const int gq = lane >> 2, tq = lane & 3;

    for (int j = tid; j < 64 * 128; j += THRP) {
        int row = j >> 7, ch = (j & 127) << 3;
        *(uint4*)&WS[row * (KK + 8) + ch] =
            *(const uint4*)&g_WdT[(size_t)(colBase + row) * KK + ch];
    }
    __syncthreads();

    const float w  = *ptr_w;
    const float pb = *ptr_b;
    const int arow = warp >> 3;               // attention row within CTA (0/1)
    const int wr = warp & 7;                  // warp-within-row (8 per row)
    const int batt = blockIdx.x * 2 + arow;

    unsigned gen = TT;
    for (int s = 0; s < TT; s++) {
        const __half* Acta = g_AdH[s & 1] + (size_t)rowBase * KK;
        __half* Anext = g_AdH[(s + 1) & 1];

        float d[2][4];
        #pragma unroll
        for (int j = 0; j < 2; j++)
            #pragma unroll
            for (int q = 0; q < 4; q++) d[j][q] = 0.f;

        gemm_f16_loop<KK>(Acta, WS, SA, d);

        #pragma unroll
        for (int ns = 0; ns < 2; ns++) {
            int c0 = colBase + nB + ns * 8 + 2 * tq;
            float bv0 = g_Bdec[c0], bv1 = g_Bdec[c0 + 1];
            float z0 = d[ns][0] + bv0;
            float z1 = d[ns][1] + bv1;
            float z2 = d[ns][2] + bv0;
            float z3 = d[ns][3] + bv1;
            float p0 = __shfl_xor_sync(0xffffffffu, z0, 1);
            float p1 = __shfl_xor_sync(0xffffffffu, z1, 1);
            float p2 = __shfl_xor_sync(0xffffffffu, z2, 1);
            float p3 = __shfl_xor_sync(0xffffffffu, z3, 1);
            if (!(tq & 1)) {
                int u = c0 >> 2;
                int r0 = rowBase + mB + gq;
                #pragma unroll
                for (int rr = 0; rr < 2; rr++) {
                    int b = r0 + rr * 8;
                    float zi = rr ? z2 : z0, zf = rr ? z3 : z1;
                    float zg = rr ? p2 : p0, zo = rr ? p3 : p1;
                    int idx = b * UU + u;
                    float c = sigf(zf) * g_c[idx] + sigf(zi) * tanhx(zg);
                    float h = sigf(zo) * tanhx(c);
                    g_c[idx] = c;
                    g_h[idx] = h;
                    Anext[b * KK + UU + u] = __float2half_rn(h);
                }
            }
        }
        gsync(++gen);

        // ---- attention: 8 warps/row, 4-way t batching, block-local online softmax ----
        {
            float hx[16];
            {
                const float4* hb = (const float4*)&g_h[batt * UU];
                float4 q0 = hb[2 * lane], q1 = hb[2 * lane + 1];
                float4 q2 = hb[2 * lane + 64], q3 = hb[2 * lane + 65];
                hx[0]=q0.x; hx[1]=q0.y; hx[2]=q0.z; hx[3]=q0.w;
                hx[4]=q1.x; hx[5]=q1.y; hx[6]=q1.z; hx[7]=q1.w;
                hx[8]=q2.x; hx[9]=q2.y; hx[10]=q2.z; hx[11]=q2.w;
                hx[12]=q3.x; hx[13]=q3.y; hx[14]=q3.z; hx[15]=q3.w;
            }
            float ca[16];
            #pragma unroll
            for (int q = 0; q < 16; q++) ca[q] = 0.f;
            float m = -3.0e38f, Zw = 0.f;

            #pragma unroll 1
            for (int it = 0; it < 8; it++) {
                const int t0 = (it << 5) + (wr << 2);
                uint4 E[4][2];
                #pragma unroll
                for (int j = 0; j < 4; j++) {
                    const uint4* ep = (const uint4*)&g_encH[((size_t)batt * TT + t0 + j) * UU];
                    E[j][0] = ep[lane];
                    E[j][1] = ep[lane + 32];
                }
                float sv[4];
                #pragma unroll
                for (int j = 0; j < 4; j++) {
                    float ex[16];
                    cvt16(E[j], ex);
                    float acc = 0.f;
                    #pragma unroll
                    for (int q = 0; q < 16; q++) acc = fmaf(ex[q], hx[q], acc);
                    sv[j] = acc;
                }
                #pragma unroll
                for (int o = 16; o; o >>= 1) {
                    sv[0] += __shfl_xor_sync(0xffffffffu, sv[0], o);
                    sv[1] += __shfl_xor_sync(0xffffffffu, sv[1], o);
                    sv[2] += __shfl_xor_sync(0xffffffffu, sv[2], o);
                    sv[3] += __shfl_xor_sync(0xffffffffu, sv[3], o);
                }
                #pragma unroll
                for (int j = 0; j < 4; j++) sv[j] = sv[j] * w + pb;
                if (lane == 0) {
                    sc[arow * TT + t0 + 0] = sv[0];
                    sc[arow * TT + t0 + 1] = sv[1];
                    sc[arow * TT + t0 + 2] = sv[2];
                    sc[arow * TT + t0 + 3] = sv[3];
                }
                float mloc = fmaxf(fmaxf(sv[0], sv[1]), fmaxf(sv[2], sv[3]));
                float mn = fmaxf(m, mloc);
                float scale = __expf(m - mn);
                float e0 = __expf(sv[0] - mn);
                float e1 = __expf(sv[1] - mn);
                float e2 = __expf(sv[2] - mn);
                float e3 = __expf(sv[3] - mn);
                Zw = Zw * scale + ((e0 + e1) + (e2 + e3));
                float ex[16];
                cvt16(E[0], ex);
                #pragma unroll
                for (int q = 0; q < 16; q++) ca[q] = ca[q] * scale + e0 * ex[q];
                cvt16(E[1], ex);
                #pragma unroll
                for (int q = 0; q < 16; q++) ca[q] = fmaf(e1, ex[q], ca[q]);
                cvt16(E[2], ex);
                #pragma unroll
                for (int q = 0; q < 16; q++) ca[q] = fmaf(e2, ex[q], ca[q]);
                cvt16(E[3], ex);
                #pragma unroll
                for (int q = 0; q < 16; q++) ca[q] = fmaf(e3, ex[q], ca[q]);
                m = mn;
            }
            if (lane == 0) { wm[warp] = m; wz[warp] = Zw; }
            {
                float4* wc = (float4*)&wctx[warp * UU];
                wc[2 * lane]      = make_float4(ca[0], ca[1], ca[2], ca[3]);
                wc[2 * lane + 1]  = make_float4(ca[4], ca[5], ca[6], ca[7]);
                wc[2 * lane + 64] = make_float4(ca[8], ca[9], ca[10], ca[11]);
                wc[2 * lane + 65] = make_float4(ca[12], ca[13], ca[14], ca[15]);
            }
            __syncthreads();

            // combine 8 warps per row; 512 threads -> one u per thread per row
            #pragma unroll
            for (int r = 0; r < 2; r++) {
                int bb = blockIdx.x * 2 + r;
                float M = wm[8 * r];
                #pragma unroll
                for (int q = 1; q < 8; q++) M = fmaxf(M, wm[8 * r + q]);
                float Zt = 0.f, x0a = 0.f;
                #pragma unroll
                for (int q = 0; q < 8; q++) {
                    int qq = 8 * r + q;
                    float e = __expf(wm[qq] - M);
                    Zt += e * wz[qq];
                    x0a += e * wctx[qq * UU + tid];
                }
                float invZ = 1.0f / Zt;
                Anext[bb * KK + tid] = __float2half_rn(x0a * invZ);
                if (tid < TT)
                    out[(size_t)bb * (TT * TT) + (size_t)s * TT + tid] =
                        __expf(sc[r * TT + tid] - M) * invZ;
            }
        }
        gsync(++gen);
    }
}

// ---------------- launch: 6 kernels ----------------
extern "C" void kernel_launch(void* const* d_in, const int* in_sizes, int n_in,
                              void* d_out, int out_size) {
    const float* inputs = (const float*)d_in[0];
    const float* score  = (const float*)d_in[1];
    const float* enc_Wx = (const float*)d_in[2];
    const float* enc_Wh = (const float*)d_in[3];
    const float* enc_b  = (const float*)d_in[4];
    const float* dec_Wx = (const float*)d_in[5];
    const float* dec_Wh = (const float*)d_in[6];
    const float* dec_b  = (const float*)d_in[7];
    const float* ptr_w  = (const float*)d_in[8];
    const float* ptr_b  = (const float*)d_in[9];
    float* out = (float*)d_out;

    cudaFuncSetAttribute(encoder_kernel, cudaFuncAttributeMaxDynamicSharedMemorySize, ENC_SMEM);
    cudaFuncSetAttribute(decoder_kernel, cudaFuncAttributeMaxDynamicSharedMemorySize, DEC_SMEM);

    prepA_kernel<<<(int)(((size_t)KK * ZZ + THR - 1) / THR), THR>>>(
        inputs, score, enc_Wx, enc_Wh, dec_Wx, dec_Wh, dec_b);
    prepX_kernel<<<(int)(((size_t)TT * BB * UU + THR - 1) / THR), THR>>>(inputs, score);

    dim3 zgrid(ZZ / 64, (TT * BB) / 128);
    zx_kernel<<<zgrid, 256>>>(enc_b);

    encoder_kernel<<<GRID, THRP, ENC_SMEM>>>();
    decprep_kernel<<<(BB * UU + THR - 1) / THR, THR>>>();
    decoder_kernel<<<GRID, THRP, DEC_SMEM>>>(ptr_w, ptr_b, out);
}

// round 17
// speedup vs baseline: 1.0170x; 1.0170x over previous
#include <cuda_runtime.h>
#include <cuda_fp16.h>
#include <math.h>

#define BB 256       // batch
#define TT 256       // timesteps
#define FF 511       // raw feature dim
#define UU 512       // units
#define ZZ 2048      // 4*U (gate-interleaved cols: n' = 4u + gate)
#define KK 1024      // decoder fused K
#define GRID 128
#define THR 256      // prep/zx block
#define THRP 512     // persistent kernels: 16 warps
#define ASTW 72      // A smem stage stride (halfs), 64-K stages

// ---------------- device scratch ----------------
__device__ float  g_Xt[(size_t)TT * BB * UU];
__device__ float  g_Zx[(size_t)TT * BB * ZZ];
__device__ __half g_encH[(size_t)BB * TT * UU];
__device__ float  g_Wxe[(size_t)UU * ZZ];
__device__ __half g_WheT[(size_t)ZZ * UU];
__device__ __half g_WdT[(size_t)ZZ * KK];
__device__ float  g_Bdec[ZZ];
__device__ __half g_AhH[2][BB * UU];
__device__ __half g_AdH[2][BB * KK];
__device__ float  g_h[BB * UU];
__device__ float  g_c[BB * UU];
__device__ float  g_x0[BB * UU];
__device__ unsigned g_gcnt[4][32];   // per-rowgroup arrive counters, 128B apart
__device__ unsigned g_gflag[4][32];  // per-rowgroup release flags, 128B apart

// ---------------- helpers ----------------
__device__ __forceinline__ float tf32r(float x) {
    unsigned r; asm("cvt.rna.tf32.f32 %0, %1;" : "=r"(r) : "f"(x));
    return __uint_as_float(r);
}
__device__ __forceinline__ float sigf(float x) { return 1.0f / (1.0f + __expf(-x)); }
__device__ __forceinline__ float tanhx(float x) { return 2.0f / (1.0f + __expf(-2.0f * x)) - 1.0f; }
__device__ __forceinline__ void h2f(unsigned v, float& a, float& b) {
    float2 f = __half22float2(*reinterpret_cast<const __half2*>(&v));
    a = f.x; b = f.y;
}
__device__ __forceinline__ void cvt16(const uint4 E[2], float ex[16]) {
    h2f(E[0].x, ex[0], ex[1]);   h2f(E[0].y, ex[2], ex[3]);
    h2f(E[0].z, ex[4], ex[5]);   h2f(E[0].w, ex[6], ex[7]);
    h2f(E[1].x, ex[8], ex[9]);   h2f(E[1].y, ex[10], ex[11]);
    h2f(E[1].z, ex[12], ex[13]); h2f(E[1].w, ex[14], ex[15]);
}

// 32-CTA row-group barrier (R15): all cross-CTA deps are group-local.
__device__ __forceinline__ void gsync(unsigned target) {
    __syncthreads();
    if (threadIdx.x == 0) {
        const int g = blockIdx.x >> 5;
        unsigned old;
        asm volatile("atom.add.acq_rel.gpu.u32 %0, [%1], 1;"
                     : "=r"(old) : "l"(&g_gcnt[g][0]) : "memory");
        if (old == 31u) {
            g_gcnt[g][0] = 0u;                 // published by the release below
            asm volatile("st.release.gpu.u32 [%0], %1;"
                         :: "l"(&g_gflag[g][0]), "r"(target) : "memory");
        } else {
            unsigned v;
            do {
                asm volatile("ld.acquire.gpu.u32 %0, [%1];"
                             : "=r"(v) : "l"(&g_gflag[g][0]) : "memory");
            } while (v < target);
        }
    }
    __syncthreads();
}

__device__ __forceinline__ void mma_tf32(float d[4], const unsigned a[4], const unsigned b[2]) {
    asm volatile("mma.sync.aligned.m16n8k8.row.col.f32.tf32.tf32.f32 "
                 "{%0,%1,%2,%3}, {%4,%5,%6,%7}, {%8,%9}, {%0,%1,%2,%3};\n"
                 : "+f"(d[0]), "+f"(d[1]), "+f"(d[2]), "+f"(d[3])
                 : "r"(a[0]), "r"(a[1]), "r"(a[2]), "r"(a[3]), "r"(b[0]), "r"(b[1]));
}
__device__ __forceinline__ void mma_f16(float d[4], const unsigned a[4], const unsigned b[2]) {
    asm volatile("mma.sync.aligned.m16n8k16.row.col.f32.f16.f16.f32 "
                 "{%0,%1,%2,%3}, {%4,%5,%6,%7}, {%8,%9}, {%0,%1,%2,%3};\n"
                 : "+f"(d[0]), "+f"(d[1]), "+f"(d[2]), "+f"(d[3])
                 : "r"(a[0]), "r"(a[1]), "r"(a[2]), "r"(a[3]), "r"(b[0]), "r"(b[1]));
}
__device__ __forceinline__ void ldsm_x4(unsigned& r0, unsigned& r1, unsigned& r2, unsigned& r3,
                                        unsigned addr) {
    asm volatile("ldmatrix.sync.aligned.m8n8.x4.shared.b16 {%0,%1,%2,%3}, [%4];"
                 : "=r"(r0), "=r"(r1), "=r"(r2), "=r"(r3) : "r"(addr));
}
__device__ __forceinline__ void cpasync16(unsigned sdst, const void* gsrc) {
    asm volatile("cp.async.cg.shared.global [%0], [%1], 16;"
                 :: "r"(sdst), "l"(gsrc) : "memory");
}

// ---------------- prep ----------------
__global__ void prepA_kernel(const float* __restrict__ inputs, const float* __restrict__ score,
                             const float* __restrict__ eWx, const float* __restrict__ eWh,
                             const float* __restrict__ dWx, const float* __restrict__ dWh,
                             const float* __restrict__ db) {
    size_t idx = (size_t)blockIdx.x * blockDim.x + threadIdx.x;
    if (idx < (size_t)KK * ZZ) {
        int k = (int)(idx / ZZ), np = (int)(idx % ZZ);
        int n = (np & 3) * UU + (np >> 2);
        float v = (k < UU) ? dWx[(size_t)k * ZZ + n] : dWh[(size_t)(k - UU) * ZZ + n];
        g_WdT[(size_t)np * KK + k] = __float2half_rn(v);
    }
    if (idx < (size_t)UU * ZZ) {
        int k = (int)(idx / ZZ), np = (int)(idx % ZZ);
        int n = (np & 3) * UU + (np >> 2);
        g_Wxe[idx] = tf32r(eWx[(size_t)k * ZZ + n]);
        g_WheT[(size_t)np * UU + k] = __float2half_rn(eWh[(size_t)k * ZZ + n]);
    }
    if (idx < ZZ) g_Bdec[idx] = db[((int)idx & 3) * UU + ((int)idx >> 2)];
    if (idx < BB * UU) {
        int i = (int)idx;
        g_AhH[0][i] = __float2half_rn(0.f);
        g_c[i] = 0.f;
        int b = i >> 9, u = i & 511;
        float s;
        if (u < FF) {
            const float* ip = inputs + (size_t)b * TT * FF + u;
            float acc = 0.f;
            #pragma unroll 4
            for (int t = 0; t < TT; t++) acc += ip[(size_t)t * FF];
            s = acc * (1.0f / TT);
        } else {
            s = score[b];
        }
        g_x0[i] = s;
    }
    if (idx < 128) {
        ((unsigned*)g_gcnt)[idx] = 0u;
        ((unsigned*)g_gflag)[idx] = 0u;
    }
}

__global__ void prepX_kernel(const float* __restrict__ inputs, const float* __restrict__ score) {
    size_t idx = (size_t)blockIdx.x * blockDim.x + threadIdx.x;
    if (idx >= (size_t)TT * BB * UU) return;
    int t = (int)(idx / (BB * UU));
    int rem = (int)(idx % (BB * UU));
    int b = rem / UU, u = rem % UU;
    float v = (u < FF) ? inputs[((size_t)b * TT + t) * FF + u] : score[b];
    g_Xt[idx] = tf32r(v);
}

// ---------------- Zx = X @ Wxe + bias ----------------
__global__ void __launch_bounds__(256) zx_kernel(const float* __restrict__ be) {
    __shared__ float SAx[2][128 * 20];
    __shared__ float SBx[2][16 * 72];
    const int tid = threadIdx.x, lane = tid & 31, wid = tid >> 5;
    const int rowBase = blockIdx.y << 7;
    const int colBase = blockIdx.x << 6;
    const int mB = (wid >> 1) << 5;
    const int nB = (wid & 1) << 5;
    const int gq = lane >> 2, tq = lane & 3;

    const int ar = tid >> 2;
    const int akq = (tid & 3) << 2;
    const int bkr = tid >> 4, bnq = (tid & 15) << 2;
    const float* aptrA = g_Xt + (size_t)(rowBase + ar) * UU + akq;
    const float* aptrB = aptrA + (size_t)64 * UU;
    const float* bptr = g_Wxe + (size_t)bkr * ZZ + colBase + bnq;

    float4 rAa0 = *(const float4*)(aptrA);
    float4 rAb0 = *(const float4*)(aptrB);
    float4 rB0  = *(const float4*)(bptr);
    float4 rAa1 = *(const float4*)(aptrA + 16);
    float4 rAb1 = *(const float4*)(aptrB + 16);
    float4 rB1  = *(const float4*)(bptr + (size_t)16 * ZZ);
    *(float4*)&SAx[0][ar * 20 + akq] = rAa0;
    *(float4*)&SAx[0][(64 + ar) * 20 + akq] = rAb0;
    *(float4*)&SBx[0][bkr * 72 + bnq] = rB0;
    __syncthreads();

    float d[2][4][4];
    #pragma unroll
    for (int i = 0; i < 2; i++)
        #pragma unroll
        for (int j = 0; j < 4; j++)
            #pragma unroll
            for (int q = 0; q < 4; q++) d[i][j][q] = 0.f;

    #pragma unroll 1
    for (int kt = 0; kt < 32; kt += 2) {
        if (kt + 2 < 32) {
            rAa0 = *(const float4*)(aptrA + (kt + 2) * 16);
            rAb0 = *(const float4*)(aptrB + (kt + 2) * 16);
            rB0  = *(const float4*)(bptr + (size_t)(kt + 2) * 16 * ZZ);
        }
        #pragma unroll
        for (int kc = 0; kc < 16; kc += 8) {
            unsigned a0[4], a1[4], bbf[4][2];
            const float* A0 = SAx[0] + (mB + gq) * 20 + kc + tq;
            a0[0] = __float_as_uint(A0[0]);      a0[1] = __float_as_uint(A0[8 * 20]);
            a0[2] = __float_as_uint(A0[4]);      a0[3] = __float_as_uint(A0[8 * 20 + 4]);
            const float* A1 = A0 + 16 * 20;
            a1[0] = __float_as_uint(A1[0]);      a1[1] = __float_as_uint(A1[8 * 20]);
            a1[2] = __float_as_uint(A1[4]);      a1[3] = __float_as_uint(A1[8 * 20 + 4]);
            const float* B0 = SBx[0] + (kc + tq) * 72 + nB + gq;
            #pragma unroll
            for (int ns = 0; ns < 4; ns++) {
                bbf[ns][0] = __float_as_uint(B0[ns * 8]);
                bbf[ns][1] = __float_as_uint(B0[4 * 72 + ns * 8]);
            }
            #pragma unroll
            for (int ns = 0; ns < 4; ns++) { mma_tf32(d[0][ns], a0, bbf[ns]); mma_tf32(d[1][ns], a1, bbf[ns]); }
        }
        *(float4*)&SAx[1][ar * 20 + akq] = rAa1;
        *(float4*)&SAx[1][(64 + ar) * 20 + akq] = rAb1;
        *(float4*)&SBx[1][bkr * 72 + bnq] = rB1;
        __syncthreads();

        if (kt + 3 < 32) {
            rAa1 = *(const float4*)(aptrA + (kt + 3) * 16);
            rAb1 = *(const float4*)(aptrB + (kt + 3) * 16);
            rB1  = *(const float4*)(bptr + (size_t)(kt + 3) * 16 * ZZ);
        }
        #pragma unroll
        for (int kc = 0; kc < 16; kc += 8) {
            unsigned a0[4], a1[4], bbf[4][2];
            const float* A0 = SAx[1] + (mB + gq) * 20 + kc + tq;
            a0[0] = __float_as_uint(A0[0]);      a0[1] = __float_as_uint(A0[8 * 20]);
            a0[2] = __float_as_uint(A0[4]);      a0[3] = __float_as_uint(A0[8 * 20 + 4]);
            const float* A1 = A0 + 16 * 20;
            a1[0] = __float_as_uint(A1[0]);      a1[1] = __float_as_uint(A1[8 * 20]);
            a1[2] = __float_as_uint(A1[4]);      a1[3] = __float_as_uint(A1[8 * 20 + 4]);
            const float* B0 = SBx[1] + (kc + tq) * 72 + nB + gq;
            #pragma unroll
            for (int ns = 0; ns < 4; ns++) {
                bbf[ns][0] = __float_as_uint(B0[ns * 8]);
                bbf[ns][1] = __float_as_uint(B0[4 * 72 + ns * 8]);
            }
            #pragma unroll
            for (int ns = 0; ns < 4; ns++) { mma_tf32(d[0][ns], a0, bbf[ns]); mma_tf32(d[1][ns], a1, bbf[ns]); }
        }
        if (kt + 2 < 32) {
            *(float4*)&SAx[0][ar * 20 + akq] = rAa0;
            *(float4*)&SAx[0][(64 + ar) * 20 + akq] = rAb0;
            *(float4*)&SBx[0][bkr * 72 + bnq] = rB0;
        }
        __syncthreads();
    }

    #pragma unroll
    for (int ms = 0; ms < 2; ms++) {
        #pragma unroll
        for (int ns = 0; ns < 4; ns++) {
            int r0 = rowBase + mB + ms * 16 + gq;
            int c0 = colBase + nB + ns * 8 + 2 * tq;
            int g0 = c0 & 3, u = c0 >> 2;
            float b0 = be[g0 * UU + u], b1 = be[(g0 + 1) * UU + u];
            float2 o1 = { d[ms][ns][0] + b0, d[ms][ns][1] + b1 };
            float2 o2 = { d[ms][ns][2] + b0, d[ms][ns][3] + b1 };
            *(float2*)&g_Zx[(size_t)r0 * ZZ + c0] = o1;
            *(float2*)&g_Zx[(size_t)(r0 + 8) * ZZ + c0] = o2;
        }
    }
}

// ---------------- 16-warp fp16 W-stationary GEMM: cp.async A pipeline, ring-4 (R15) ----------------
template<int KD>
__device__ __forceinline__ void gemm_f16_loop(const __half* __restrict__ Acta,
                                              const __half* __restrict__ WS,
                                              __half* __restrict__ SA,
                                              float d[2][4]) {
    const int tid = threadIdx.x, lane = tid & 31, wid = tid >> 5;
    const int mB = (wid >> 2) << 4;
    const int nB = (wid & 3) << 4;
    const int WSTR = KD + 8;
    const int aRow = (lane & 7) + ((lane >> 3) & 1) * 8;
    const int aK   = (lane >> 4) << 3;
    const int bN   = ((lane >> 4) << 3) + (lane & 7);
    const int bK   = ((lane >> 3) & 1) << 3;

    unsigned saBase = (unsigned)__cvta_generic_to_shared(SA);
    unsigned wsAddr = (unsigned)__cvta_generic_to_shared(WS)
                    + (unsigned)(((nB + bN) * WSTR + bK) * 2);
    unsigned aAddr = saBase + (unsigned)(((mB + aRow) * ASTW + aK) * 2);

    const int r = tid >> 3, j8 = (tid & 7) << 3;   // 64 rows x 64 halfs, 1 uint4/thread
    const __half* ap = Acta + (size_t)r * KD + j8;
    const unsigned sdst = saBase + (unsigned)((r * ASTW + j8) * 2);
    const unsigned SLOT = (unsigned)(64 * ASTW * 2);

    constexpr int S = KD / 64;                     // 8 (enc) / 16 (dec)
    cpasync16(sdst + 0 * SLOT, ap);
    asm volatile("cp.async.commit_group;" ::: "memory");
    cpasync16(sdst + 1 * SLOT, ap + 64);
    asm volatile("cp.async.commit_group;" ::: "memory");

    #pragma unroll 1
    for (int s = 0; s < S; s++) {
        if (s + 2 < S) cpasync16(sdst + ((s + 2) & 3) * SLOT, ap + (s + 2) * 64);
        asm volatile("cp.async.commit_group;" ::: "memory");
        asm volatile("cp.async.wait_group 2;" ::: "memory");
        __syncthreads();

        unsigned sa = aAddr + (unsigned)(s & 3) * SLOT;
        unsigned wk = wsAddr + (unsigned)((s << 6) * 2);
        #pragma unroll
        for (int kc = 0; kc < 64; kc += 16) {
            unsigned a0[4], bb[4];
            ldsm_x4(a0[0], a0[1], a0[2], a0[3], sa + kc * 2);
            ldsm_x4(bb[0], bb[1], bb[2], bb[3], wk + kc * 2);
            unsigned b0[2] = { bb[0], bb[1] };
            unsigned b1[2] = { bb[2], bb[3] };
            mma_f16(d[0], a0, b0);
            mma_f16(d[1], a0, b1);
        }
    }
    __syncthreads();
}

// ---------------- persistent encoder (512 threads) ----------------
#define ENC_WS_H (64 * (UU + 8))
#define ENC_SMEM ((ENC_WS_H + 4 * 64 * ASTW) * 2)

__global__ void __launch_bounds__(THRP, 1) encoder_kernel() {
    extern __shared__ __half es[];
    __half* WS = es;
    __half* SA = es + ENC_WS_H;

    const int tid = threadIdx.x, lane = tid & 31, wid = tid >> 5;
    const int rowBase = (blockIdx.x >> 5) << 6;
    const int colBase = (blockIdx.x & 31) << 6;
    const int mB = (wid >> 2) << 4;
    const int nB = (wid & 3) << 4;
    const int gq = lane >> 2, tq = lane & 3;

    for (int j = tid; j < 64 * 64; j += THRP) {
        int row = j >> 6, ch = (j & 63) << 3;
        *(uint4*)&WS[row * (UU + 8) + ch] =
            *(const uint4*)&g_WheT[(size_t)(colBase + row) * UU + ch];
    }
    __syncthreads();

    unsigned gen = 0;
    for (int t = 0; t < TT; t++) {
        const __half* Acta = g_AhH[t & 1] + (size_t)rowBase * UU;
        __half* An = g_AhH[(t + 1) & 1];

        float d[2][4];
        #pragma unroll
        for (int j = 0; j < 2; j++)
            #pragma unroll
            for (int q = 0; q < 4; q++) d[j][q] = 0.f;

        gemm_f16_loop<UU>(Acta, WS, SA, d);

        // epilogue: both lanes active — even lane computes row r0, odd lane row r0+8
        #pragma unroll
        for (int ns = 0; ns < 2; ns++) {
            int r0 = rowBase + mB + gq;
            int c0 = colBase + nB + ns * 8 + 2 * tq;
            const float* zx = &g_Zx[((size_t)t * BB + r0) * ZZ + c0];
            float2 zxa = *(const float2*)zx;
            float2 zxb = *(const float2*)(zx + (size_t)8 * ZZ);
            float z0 = d[ns][0] + zxa.x;
            float z1 = d[ns][1] + zxa.y;
            float z2 = d[ns][2] + zxb.x;
            float z3 = d[ns][3] + zxb.y;
            float p0 = __shfl_xor_sync(0xffffffffu, z0, 1);
            float p1 = __shfl_xor_sync(0xffffffffu, z1, 1);
            float p2 = __shfl_xor_sync(0xffffffffu, z2, 1);
            float p3 = __shfl_xor_sync(0xffffffffu, z3, 1);
            const bool odd = tq & 1;
            int u = c0 >> 2;
            int b = r0 + (odd ? 8 : 0);
            float zi = odd ? p2 : z0;
            float zf = odd ? p3 : z1;
            float zg = odd ? z2 : p0;
            float zo = odd ? z3 : p1;
            int idx = b * UU + u;
            float c = sigf(zf) * g_c[idx] + sigf(zi) * tanhx(zg);
            float h = sigf(zo) * tanhx(c);
            g_c[idx] = c;
            __half hh = __float2half_rn(h);
            An[idx] = hh;
            g_encH[((size_t)b * TT + t) * UU + u] = hh;
        }
        gsync(++gen);
    }
}

// ---------------- decoder prologue ----------------
__global__ void decprep_kernel() {
    int idx = blockIdx.x * THR + threadIdx.x;
    if (idx >= BB * UU) return;
    int b = idx >> 9, u = idx & 511;
    g_AdH[0][b * KK + u] = __float2half_rn(g_x0[idx]);
    g_AdH[0][b * KK + UU + u] = g_AhH[0][idx];
}

// ---------------- persistent decoder (512 threads, uniform phases) ----------------
#define DEC_WS_H (64 * (KK + 8))
#define DEC_SA_H (4 * 64 * ASTW)
#define DEC_SMEM (DEC_WS_H * 2 + DEC_SA_H * 2 + (16 * UU + 2 * TT + 40) * 4)

__global__ void __launch_bounds__(THRP, 1) decoder_kernel(
    const float* __restrict__ ptr_w, const float* __restrict__ ptr_b,
    float* __restrict__ out) {
    extern __shared__ __half ds[];
    __half* WS = ds;
    __half* SA = ds + DEC_WS_H;
    float* wctx = (float*)(ds + DEC_WS_H + DEC_SA_H);   // [16][512]
    float* sc   = wctx + 16 * UU;                       // [2][256]
    float* wm   = sc + 2 * TT;                          // [16]
    float* wz   = wm + 16;                              // [16]

    const int tid = threadIdx.x, lane = tid & 31, warp = tid >> 5;
    const int rowBase = (blockIdx.x >> 5) << 6;
    const int colBase = (blockIdx.x & 31) << 6;
    const int mB = (warp >> 2) << 4;
    const int nB = (warp & 3) << 4;
    const int gq = lane >> 2, tq = lane & 3;

    for (int j = tid; j < 64 * 128; j += THRP) {
        int row = j >> 7, ch = (j & 127) << 3;
        *(uint4*)&WS[row * (KK + 8) + ch] =
            *(const uint4*)&g_WdT[(size_t)(colBase + row) * KK + ch];
    }
    __syncthreads();

    const float w  = *ptr_w;
    const float pb = *ptr_b;
    const int arow = warp >> 3;               // attention row within CTA (0/1)
    const int wr = warp & 7;                  // warp-within-row (8 per row)
    const int batt = blockIdx.x * 2 + arow;

    unsigned gen = TT;
    for (int s = 0; s < TT; s++) {
        const __half* Acta = g_AdH[s & 1] + (size_t)rowBase * KK;
        __half* Anext = g_AdH[(s + 1) & 1];

        float d[2][4];
        #pragma unroll
        for (int j = 0; j < 2; j++)
            #pragma unroll
            for (int q = 0; q < 4; q++) d[j][q] = 0.f;

        gemm_f16_loop<KK>(Acta, WS, SA, d);

        // epilogue: both lanes active — even lane row r0, odd lane row r0+8
        #pragma unroll
        for (int ns = 0; ns < 2; ns++) {
            int c0 = colBase + nB + ns * 8 + 2 * tq;
            float bv0 = g_Bdec[c0], bv1 = g_Bdec[c0 + 1];
            float z0 = d[ns][0] + bv0;
            float z1 = d[ns][1] + bv1;
            float z2 = d[ns][2] + bv0;
            float z3 = d[ns][3] + bv1;
            float p0 = __shfl_xor_sync(0xffffffffu, z0, 1);
            float p1 = __shfl_xor_sync(0xffffffffu, z1, 1);
            float p2 = __shfl_xor_sync(0xffffffffu, z2, 1);
            float p3 = __shfl_xor_sync(0xffffffffu, z3, 1);
            const bool odd = tq & 1;
            int u = c0 >> 2;
            int r0 = rowBase + mB + gq;
            int b = r0 + (odd ? 8 : 0);
            float zi = odd ? p2 : z0;
            float zf = odd ? p3 : z1;
            float zg = odd ? z2 : p0;
            float zo = odd ? z3 : p1;
            int idx = b * UU + u;
            float c = sigf(zf) * g_c[idx] + sigf(zi) * tanhx(zg);
            float h = sigf(zo) * tanhx(c);
            g_c[idx] = c;
            g_h[idx] = h;
            Anext[b * KK + UU + u] = __float2half_rn(h);
        }
        gsync(++gen);

        // ---- attention: 8 warps/row, 4-way t batching, block-local online softmax ----
        {
            float hx[16];
            {
                const float4* hb = (const float4*)&g_h[batt * UU];
                float4 q0 = hb[2 * lane], q1 = hb[2 * lane + 1];
                float4 q2 = hb[2 * lane + 64], q3 = hb[2 * lane + 65];
                hx[0]=q0.x; hx[1]=q0.y; hx[2]=q0.z; hx[3]=q0.w;
                hx[4]=q1.x; hx[5]=q1.y; hx[6]=q1.z; hx[7]=q1.w;
                hx[8]=q2.x; hx[9]=q2.y; hx[10]=q2.z; hx[11]=q2.w;
                hx[12]=q3.x; hx[13]=q3.y; hx[14]=q3.z; hx[15]=q3.w;
            }
            float ca[16];
            #pragma unroll
            for (int q = 0; q < 16; q++) ca[q] = 0.f;
            float m = -3.0e38f, Zw = 0.f;

            #pragma unroll 1
            for (int it = 0; it < 8; it++) {
                const int t0 = (it << 5) + (wr << 2);
                uint4 E[4][2];
                #pragma unroll
                for (int j = 0; j < 4; j++) {
                    const uint4* ep = (const uint4*)&g_encH[((size_t)batt * TT + t0 + j) * UU];
                    E[j][0] = ep[lane];
                    E[j][1] = ep[lane + 32];
                }
                float sv[4];
                #pragma unroll
                for (int j = 0; j < 4; j++) {
                    float ex[16];
                    cvt16(E[j], ex);
                    float acc = 0.f;
                    #pragma unroll
                    for (int q = 0; q < 16; q++) acc = fmaf(ex[q], hx[q], acc);
                    sv[j] = acc;
                }
                #pragma unroll
                for (int o = 16; o; o >>= 1) {
                    sv[0] += __shfl_xor_sync(0xffffffffu, sv[0], o);
                    sv[1] += __shfl_xor_sync(0xffffffffu, sv[1], o);
                    sv[2] += __shfl_xor_sync(0xffffffffu, sv[2], o);
                    sv[3] += __shfl_xor_sync(0xffffffffu, sv[3], o);
                }
                #pragma unroll
                for (int j = 0; j < 4; j++) sv[j] = sv[j] * w + pb;
                if (lane == 0) {
                    sc[arow * TT + t0 + 0] = sv[0];
                    sc[arow * TT + t0 + 1] = sv[1];
                    sc[arow * TT + t0 + 2] = sv[2];
                    sc[arow * TT + t0 + 3] = sv[3];
                }
                float mloc = fmaxf(fmaxf(sv[0], sv[1]), fmaxf(sv[2], sv[3]));
                float mn = fmaxf(m, mloc);
                float scale = __expf(m - mn);
                float e0 = __expf(sv[0] - mn);
                float e1 = __expf(sv[1] - mn);
                float e2 = __expf(sv[2] - mn);
                float e3 = __expf(sv[3] - mn);
                Zw = Zw * scale + ((e0 + e1) + (e2 + e3));
                float ex[16];
                cvt16(E[0], ex);
                #pragma unroll
                for (int q = 0; q < 16; q++) ca[q] = ca[q] * scale + e0 * ex[q];
                cvt16(E[1], ex);
                #pragma unroll
                for (int q = 0; q < 16; q++) ca[q] = fmaf(e1, ex[q], ca[q]);
                cvt16(E[2], ex);
                #pragma unroll
                for (int q = 0; q < 16; q++) ca[q] = fmaf(e2, ex[q], ca[q]);
                cvt16(E[3], ex);
                #pragma unroll
                for (int q = 0; q < 16; q++) ca[q] = fmaf(e3, ex[q], ca[q]);
                m = mn;
            }
            if (lane == 0) { wm[warp] = m; wz[warp] = Zw; }
            {
                float4* wc = (float4*)&wctx[warp * UU];
                wc[2 * lane]      = make_float4(ca[0], ca[1], ca[2], ca[3]);
                wc[2 * lane + 1]  = make_float4(ca[4], ca[5], ca[6], ca[7]);
                wc[2 * lane + 64] = make_float4(ca[8], ca[9], ca[10], ca[11]);
                wc[2 * lane + 65] = make_float4(ca[12], ca[13], ca[14], ca[15]);
            }
            __syncthreads();

            // combine 8 warps per row; 512 threads -> one u per thread per row
            #pragma unroll
            for (int r = 0; r < 2; r++) {
                int bb = blockIdx.x * 2 + r;
                float M = wm[8 * r];
                #pragma unroll
                for (int q = 1; q < 8; q++) M = fmaxf(M, wm[8 * r + q]);
                float Zt = 0.f, x0a = 0.f;
                #pragma unroll
                for (int q = 0; q < 8; q++) {
                    int qq = 8 * r + q;
                    float e = __expf(wm[qq] - M);
                    Zt += e * wz[qq];
                    x0a += e * wctx[qq * UU + tid];
                }
                float invZ = 1.0f / Zt;
                Anext[bb * KK + tid] = __float2half_rn(x0a * invZ);
                if (tid < TT)
                    out[(size_t)bb * (TT * TT) + (size_t)s * TT + tid] =
                        __expf(sc[r * TT + tid] - M) * invZ;
            }
        }
        gsync(++gen);
    }
}

// ---------------- launch: 6 kernels ----------------
extern "C" void kernel_launch(void* const* d_in, const int* in_sizes, int n_in,
                              void* d_out, int out_size) {
    const float* inputs = (const float*)d_in[0];
    const float* score  = (const float*)d_in[1];
    const float* enc_Wx = (const float*)d_in[2];
    const float* enc_Wh = (const float*)d_in[3];
    const float* enc_b  = (const float*)d_in[4];
    const float* dec_Wx = (const float*)d_in[5];
    const float* dec_Wh = (const float*)d_in[6];
    const float* dec_b  = (const float*)d_in[7];
    const float* ptr_w  = (const float*)d_in[8];
    const float* ptr_b  = (const float*)d_in[9];
    float* out = (float*)d_out;

    cudaFuncSetAttribute(encoder_kernel, cudaFuncAttributeMaxDynamicSharedMemorySize, ENC_SMEM);
    cudaFuncSetAttribute(decoder_kernel, cudaFuncAttributeMaxDynamicSharedMemorySize, DEC_SMEM);

    prepA_kernel<<<(int)(((size_t)KK * ZZ + THR - 1) / THR), THR>>>(
        inputs, score, enc_Wx, enc_Wh, dec_Wx, dec_Wh, dec_b);
    prepX_kernel<<<(int)(((size_t)TT * BB * UU + THR - 1) / THR), THR>>>(inputs, score);

    dim3 zgrid(ZZ / 64, (TT * BB) / 128);
    zx_kernel<<<zgrid, 256>>>(enc_b);

    encoder_kernel<<<GRID, THRP, ENC_SMEM>>>();
    decprep_kernel<<<(BB * UU + THR - 1) / THR, THR>>>();
    decoder_kernel<<<GRID, THRP, DEC_SMEM>>>(ptr_w, ptr_b, out);
}